// round 6
// baseline (speedup 1.0000x reference)
#include <cuda_runtime.h>
#include <cuda_fp16.h>
#include <math.h>
#include <stdint.h>

// Problem constants
#define BB 8192
#define NN 12
#define HH 512
#define TWO_H 1024
#define VV 256
#define LN_EPS 1e-5f

// ---------------------------------------------------------------------------
// Device scratch: fp16 activations + fp16 W^T
// ---------------------------------------------------------------------------
__device__ __align__(1024) __half g_a[(size_t)NN * BB * TWO_H];
__device__ __align__(1024) __half g_w[(size_t)NN * VV * TWO_H];

// ---------------------------------------------------------------------------
// PTX helpers (base-PTX only: cp.async, ldmatrix, mma.sync — all sm_80+)
// ---------------------------------------------------------------------------
__device__ __forceinline__ uint32_t smem_u32(const void* p) {
    uint32_t a;
    asm("{ .reg .u64 t; cvta.to.shared.u64 t, %1; cvt.u32.u64 %0, t; }" : "=r"(a) : "l"(p));
    return a;
}
__device__ __forceinline__ void cp_async16(uint32_t dst, const void* src) {
    asm volatile("cp.async.cg.shared.global [%0], [%1], 16;" :: "r"(dst), "l"(src) : "memory");
}
#define CP_ASYNC_COMMIT() asm volatile("cp.async.commit_group;" ::: "memory")

__device__ __forceinline__ void ldsm_x4(uint32_t& r0, uint32_t& r1, uint32_t& r2, uint32_t& r3,
                                        uint32_t addr) {
    asm volatile("ldmatrix.sync.aligned.m8n8.x4.shared.b16 {%0,%1,%2,%3}, [%4];"
                 : "=r"(r0), "=r"(r1), "=r"(r2), "=r"(r3) : "r"(addr));
}
__device__ __forceinline__ void mma_f16(float* d, const uint32_t* a, const uint32_t* b) {
    asm volatile(
        "mma.sync.aligned.m16n8k16.row.col.f32.f16.f16.f32 "
        "{%0,%1,%2,%3}, {%4,%5,%6,%7}, {%8,%9}, {%0,%1,%2,%3};"
        : "+f"(d[0]), "+f"(d[1]), "+f"(d[2]), "+f"(d[3])
        : "r"(a[0]), "r"(a[1]), "r"(a[2]), "r"(a[3]), "r"(b[0]), "r"(b[1]));
}

#define SWZ128(o) ((o) ^ (((o) >> 3) & 0x70))

// ---------------------------------------------------------------------------
// Kernel 1: gather + exclusive prefix sum + LayerNorm + exact GELU -> fp16
// One CTA per batch row b. 256 threads x 4 dims each.
// One barrier per n-iteration: warp shfl reduce -> parity-buffered partials
// -> all threads redundantly sum 8 partials (parallel, no serialization).
// Embedding gather for the NEXT prefix state is issued at iteration top so
// DRAM latency overlaps the reduction + GELU compute.
// ---------------------------------------------------------------------------
__global__ void __launch_bounds__(256) act_kernel(
    const float* __restrict__ input_embedding,  // (B, H)
    const int* __restrict__ features,           // (B, N)
    const float* __restrict__ emb_tables,       // (N, V, H)
    const float* __restrict__ ln_gamma,         // (2H,)
    const float* __restrict__ ln_beta)          // (2H,)
{
    const int b = blockIdx.x;
    const int tid = threadIdx.x;
    const int i = tid * 4;
    const bool is_ctx = (tid < 128);
    const int warp = tid >> 5;
    const int lane = tid & 31;

    __shared__ float2 sh_part[2][8];   // parity-double-buffered {sum, sumsq}
    __shared__ int sh_feat[NN];

    // preload all 12 feature ids once
    if (tid < NN) sh_feat[tid] = features[b * NN + tid];

    float4 vals;
    if (is_ctx) {
        vals = *reinterpret_cast<const float4*>(input_embedding + (size_t)b * HH + i);
    } else {
        vals = make_float4(0.f, 0.f, 0.f, 0.f);
    }
    const float4 g  = *reinterpret_cast<const float4*>(ln_gamma + i);
    const float4 be = *reinterpret_cast<const float4*>(ln_beta + i);

    const float inv = 1.0f / (float)TWO_H;
    __syncthreads();   // sh_feat ready

    for (int n = 0; n < NN; n++) {
        // issue the gather early: e is consumed only at the END of this iter
        float4 e = make_float4(0.f, 0.f, 0.f, 0.f);
        if (!is_ctx) {
            const int feat = sh_feat[n];
            e = *reinterpret_cast<const float4*>(
                emb_tables + ((size_t)n * VV + feat) * HH + (i - HH));
        }

        float s1 = vals.x + vals.y + vals.z + vals.w;
        float s2 = vals.x * vals.x + vals.y * vals.y + vals.z * vals.z + vals.w * vals.w;
        #pragma unroll
        for (int o = 16; o > 0; o >>= 1) {
            s1 += __shfl_xor_sync(0xFFFFFFFFu, s1, o);
            s2 += __shfl_xor_sync(0xFFFFFFFFu, s2, o);
        }
        const int p = n & 1;
        if (lane == 0) sh_part[p][warp] = make_float2(s1, s2);
        __syncthreads();

        float ta = 0.f, tb = 0.f;
        #pragma unroll
        for (int w = 0; w < 8; w++) {
            const float2 pr = sh_part[p][w];
            ta += pr.x; tb += pr.y;
        }
        const float mu = ta * inv;
        const float rstd = rsqrtf(tb * inv - mu * mu + LN_EPS);

        float yv[4] = {vals.x, vals.y, vals.z, vals.w};
        float gv[4] = {g.x, g.y, g.z, g.w};
        float bv[4] = {be.x, be.y, be.z, be.w};
        __half h4[4];
        #pragma unroll
        for (int j = 0; j < 4; j++) {
            float y = (yv[j] - mu) * rstd * gv[j] + bv[j];
            float a = 0.5f * y * (1.0f + erff(y * 0.70710678118654752f));
            h4[j] = __float2half(a);
        }
        const size_t ofs = ((size_t)n * BB + b) * TWO_H + i;
        *reinterpret_cast<uint2*>(g_a + ofs) = *reinterpret_cast<uint2*>(h4);

        vals.x += e.x; vals.y += e.y; vals.z += e.z; vals.w += e.w;
    }
}

// ---------------------------------------------------------------------------
// Kernel 2: transpose + fp16 convert pred_W (N,2H,V) -> W^T (N,V,2H)
// ---------------------------------------------------------------------------
__global__ void __launch_bounds__(256) wconv_kernel(const float* __restrict__ pred_W)
{
    __shared__ float tile[32][33];
    const int n  = blockIdx.z;
    const int k0 = blockIdx.x * 32;
    const int v0 = blockIdx.y * 32;
    const int tx = threadIdx.x, ty = threadIdx.y;

    #pragma unroll
    for (int r = 0; r < 4; r++) {
        const int k = k0 + ty + r * 8;
        tile[ty + r * 8][tx] = pred_W[((size_t)n * TWO_H + k) * VV + v0 + tx];
    }
    __syncthreads();
    #pragma unroll
    for (int r = 0; r < 4; r++) {
        const int v = v0 + ty + r * 8;
        const float w = tile[tx][ty + r * 8];
        g_w[((size_t)n * VV + v) * TWO_H + k0 + tx] = __float2half(w);
    }
}

// ---------------------------------------------------------------------------
// Kernel 3: mma.sync fp16 GEMM, single term: C = A*W^T, fp32 accum.
// CTA tile 128(M)x128(N), K-chunk 64, 3-stage cp.async pipeline, 2 CTAs/SM.
// 8 warps: warpM = wid&3 (32 rows), warpN = wid>>2 (64 cols).
// ---------------------------------------------------------------------------
#define KCH 64
#define NCHUNK (TWO_H / KCH)            // 16
#define TILE_BYTES (128 * 128)          // 16KB each (128 rows x 64 fp16)
#define STAGE_BYTES (2 * TILE_BYTES)    // A, W = 32KB
#define NSTAGE 3
#define GEMM_DYN_SMEM (NSTAGE * STAGE_BYTES) // 96KB

__global__ void __launch_bounds__(256, 2) gemm_mma_kernel(
    const float* __restrict__ pred_b,   // (N, V)
    float* __restrict__ out)            // (B, N, V)
{
    extern __shared__ __align__(1024) char dynsmem[];
    const int vtile = blockIdx.x;       // 0..1
    const int mtile = blockIdx.y;       // 0..63
    const int n     = blockIdx.z;       // 0..11
    const int tid = threadIdx.x;
    const int wid = tid >> 5;
    const int lid = tid & 31;
    const int warpM = wid & 3;          // 0..3 -> 32 rows
    const int warpN = wid >> 2;         // 0..1 -> 64 cols

    const uint32_t base = smem_u32(dynsmem);

    const __half* A = g_a + ((size_t)n * BB + (size_t)mtile * 128) * TWO_H;
    const __half* W = g_w + ((size_t)n * VV + (size_t)vtile * 128) * TWO_H;

    const int l_row[4] = { (0 * 256 + tid) >> 3, (1 * 256 + tid) >> 3,
                           (2 * 256 + tid) >> 3, (3 * 256 + tid) >> 3 };
    const int l_seg = tid & 7;

    float acc[2][8][4];
    #pragma unroll
    for (int f = 0; f < 2; f++)
        #pragma unroll
        for (int nf = 0; nf < 8; nf++)
            #pragma unroll
            for (int j = 0; j < 4; j++) acc[f][nf][j] = 0.f;

    const int lrow = lid & 15;
    const int khalf = lid >> 4;

    #define LOAD_STAGE(c, buf) do { \
        const uint32_t sA = base + (buf) * STAGE_BYTES; \
        const uint32_t sW = sA + TILE_BYTES; \
        const int kofs = (c) * KCH; \
        _Pragma("unroll") \
        for (int t = 0; t < 4; t++) { \
            const int row = l_row[t]; \
            const uint32_t d = SWZ128(row * 128 + l_seg * 16); \
            const size_t go = (size_t)row * TWO_H + kofs + l_seg * 8; \
            cp_async16(sA + d, A + go); \
            cp_async16(sW + d, W + go); \
        } \
        CP_ASYNC_COMMIT(); \
    } while (0)

    LOAD_STAGE(0, 0);
    LOAD_STAGE(1, 1);

    int buf = 0;
    for (int c = 0; c < NCHUNK; c++) {
        if (c + 2 < NCHUNK) {
            LOAD_STAGE(c + 2, (c + 2) % NSTAGE);
            asm volatile("cp.async.wait_group 2;" ::: "memory");
        } else if (c + 1 < NCHUNK) {
            asm volatile("cp.async.wait_group 1;" ::: "memory");
        } else {
            asm volatile("cp.async.wait_group 0;" ::: "memory");
        }
        __syncthreads();

        const uint32_t sA = base + buf * STAGE_BYTES;
        const uint32_t sW = sA + TILE_BYTES;

        #pragma unroll
        for (int ks = 0; ks < 4; ks++) {
            uint32_t ah[2][4], bh[8][2];
            #pragma unroll
            for (int f = 0; f < 2; f++) {
                const int row = warpM * 32 + f * 16 + lrow;
                const uint32_t d = SWZ128(row * 128 + ks * 32 + khalf * 16);
                ldsm_x4(ah[f][0], ah[f][1], ah[f][2], ah[f][3], sA + d);
            }
            #pragma unroll
            for (int gB = 0; gB < 4; gB++) {
                const int row = warpN * 64 + gB * 16 + lrow;
                const uint32_t d = SWZ128(row * 128 + ks * 32 + khalf * 16);
                uint32_t t0, t1, t2, t3;
                ldsm_x4(t0, t1, t2, t3, sW + d);
                bh[gB * 2][0] = t0; bh[gB * 2 + 1][0] = t1;
                bh[gB * 2][1] = t2; bh[gB * 2 + 1][1] = t3;
            }
            #pragma unroll
            for (int f = 0; f < 2; f++)
                #pragma unroll
                for (int nf = 0; nf < 8; nf++)
                    mma_f16(acc[f][nf], ah[f], bh[nf]);
        }
        __syncthreads();
        buf = (buf + 1 == NSTAGE) ? 0 : buf + 1;
    }

    // Epilogue: bias add + store.
    const int g  = lid >> 2;
    const int tg = lid & 3;
    float2 bias[8];
    #pragma unroll
    for (int nf = 0; nf < 8; nf++) {
        const int v = vtile * 128 + warpN * 64 + nf * 8 + tg * 2;
        bias[nf] = *reinterpret_cast<const float2*>(pred_b + n * VV + v);
    }
    #pragma unroll
    for (int f = 0; f < 2; f++) {
        const int m0 = mtile * 128 + warpM * 32 + f * 16 + g;
        #pragma unroll
        for (int nf = 0; nf < 8; nf++) {
            const int v = vtile * 128 + warpN * 64 + nf * 8 + tg * 2;
            float* o0 = out + ((size_t)m0 * NN + n) * VV + v;
            float* o1 = out + ((size_t)(m0 + 8) * NN + n) * VV + v;
            float2 r0 = make_float2(acc[f][nf][0] + bias[nf].x, acc[f][nf][1] + bias[nf].y);
            float2 r1 = make_float2(acc[f][nf][2] + bias[nf].x, acc[f][nf][3] + bias[nf].y);
            *reinterpret_cast<float2*>(o0) = r0;
            *reinterpret_cast<float2*>(o1) = r1;
        }
    }
}

// ---------------------------------------------------------------------------
extern "C" void kernel_launch(void* const* d_in, const int* in_sizes, int n_in,
                              void* d_out, int out_size)
{
    const float* input_embedding = (const float*)d_in[0];  // (B, H)
    const int*   features        = (const int*)d_in[1];    // (B, N)
    const float* emb_tables      = (const float*)d_in[2];  // (N, V, H)
    const float* ln_gamma        = (const float*)d_in[3];  // (2H,)
    const float* ln_beta         = (const float*)d_in[4];  // (2H,)
    const float* pred_W          = (const float*)d_in[5];  // (N, 2H, V)
    const float* pred_b          = (const float*)d_in[6];  // (N, V)
    float* out = (float*)d_out;                            // (B, N, V)

    cudaFuncSetAttribute(gemm_mma_kernel,
                         cudaFuncAttributeMaxDynamicSharedMemorySize, GEMM_DYN_SMEM);

    wconv_kernel<<<dim3(TWO_H / 32, VV / 32, NN), dim3(32, 8)>>>(pred_W);
    act_kernel<<<BB, 256>>>(input_embedding, features, emb_tables, ln_gamma, ln_beta);
    gemm_mma_kernel<<<dim3(2, 64, NN), 256, GEMM_DYN_SMEM>>>(pred_b, out);
}